// round 13
// baseline (speedup 1.0000x reference)
#include <cuda_runtime.h>
#include <cuda_fp16.h>
#include <cstdint>

#define H 512
#define O 512
#define E 16
#define N_MAX 32768

#define BM 128          // tokens per CTA tile
#define BN 128          // outputs per CTA tile
#define BKT 64          // fp16 k-elements per smem tile (128B per row)
#define KTILES (H / BKT)
#define MAX_TILES 272

// ---------------- device scratch ----------------
__device__ int g_count[E];          // zeroed static; tile_kernel re-zeroes each run
__device__ int g_ecnt[E];
__device__ int g_perm[E * N_MAX];   // fixed-stride per-expert buckets (2 MB)
__device__ int g_tile_e[MAX_TILES];
__device__ int g_tile_m0[MAX_TILES];
__device__ int g_ntiles;

// pre-converted fp16 copies
__device__ uint16_t g_xhi[N_MAX * H];   // 32 MB
__device__ uint16_t g_whi[E * O * H];   // 8 MB

// ---------------- helpers ----------------
__device__ __forceinline__ uint32_t smem_u32(const void* p) {
    uint32_t a;
    asm("{ .reg .u64 t; cvta.to.shared.u64 t, %1; cvt.u32.u64 %0, t; }" : "=r"(a) : "l"(p));
    return a;
}
#define SWZ(o) ((o) ^ (((o) >> 3) & 0x70))

__device__ __forceinline__ uint32_t cvt_h2(float a, float b) {
    uint32_t hi;
    asm("cvt.rn.f16x2.f32 %0, %1, %2;" : "=r"(hi) : "f"(b), "f"(a));
    return hi;
}

__device__ __forceinline__ void ldsm4(uint32_t* r, uint32_t addr) {
    asm volatile("ldmatrix.sync.aligned.m8n8.x4.shared.b16 {%0,%1,%2,%3}, [%4];"
                 : "=r"(r[0]), "=r"(r[1]), "=r"(r[2]), "=r"(r[3]) : "r"(addr));
}

__device__ __forceinline__ void mma_f16(float* d, const uint32_t* a, const uint32_t* b) {
    asm volatile(
        "mma.sync.aligned.m16n8k16.row.col.f32.f16.f16.f32 "
        "{%0,%1,%2,%3}, {%4,%5,%6,%7}, {%8,%9}, {%0,%1,%2,%3};"
        : "+f"(d[0]), "+f"(d[1]), "+f"(d[2]), "+f"(d[3])
        : "r"(a[0]), "r"(a[1]), "r"(a[2]), "r"(a[3]), "r"(b[0]), "r"(b[1]));
}

__device__ __forceinline__ void cp16(uint32_t dst, const void* src, int srcsz) {
    asm volatile("cp.async.cg.shared.global [%0], [%1], 16, %2;"
                 :: "r"(dst), "l"(src), "r"(srcsz) : "memory");
}
#define CP_COMMIT() asm volatile("cp.async.commit_group;" ::: "memory")
#define CP_WAIT(n)  asm volatile("cp.async.wait_group %0;" :: "n"(n) : "memory")

// ---------------- smem layout (GEMM): 3 stages x 32KB -> 2 CTAs/SM ----------
#define STAGE_SZ 32768
#define A_HI 0
#define B_HI 16384
#define SMEM_TOTAL (1024 + 3 * STAGE_SZ)   // 99328 -> 2 CTAs/SM
#define EPI_STRIDE 132

// ---------------- gate: finalize one token (argmax + guard + bucket) --------
__device__ __forceinline__ void finalize_token(
    const float* __restrict__ xr, const float* __restrict__ Wgs,
    const float* __restrict__ bg, float* acc, int lane8, uint32_t mask8, int tok) {
    // butterfly reduce over the 8 lanes (all lanes identical after)
#pragma unroll
    for (int e = 0; e < E; e++) {
        acc[e] += __shfl_xor_sync(mask8, acc[e], 1);
        acc[e] += __shfl_xor_sync(mask8, acc[e], 2);
        acc[e] += __shfl_xor_sync(mask8, acc[e], 4);
        acc[e] += bg[e];
    }

    int best = 0;
    float bv = acc[0];
#pragma unroll
    for (int e = 1; e < E; e++)
        if (acc[e] > bv) { bv = acc[e]; best = e; }

    int sec = (best == 0) ? 1 : 0;
    float sv = acc[sec];
#pragma unroll
    for (int e = 0; e < E; e++)
        if (e != best && acc[e] > sv) { sv = acc[e]; sec = e; }

    if (bv - sv < 1e-3f) {
        // near-tie: 8-lane cooperative fp64 recompute of both candidates (cold)
        int ea = min(best, sec), eb = max(best, sec);
        double la = 0.0, lb = 0.0;
#pragma unroll 4
        for (int i = 0; i < H / 32; i++) {
            int k = i * 32 + lane8 * 4;
            float4 xv = *(const float4*)(xr + k);
            const float* wa = &Wgs[ea * H + k];
            const float* wb = &Wgs[eb * H + k];
            la += (double)xv.x * wa[0] + (double)xv.y * wa[1] +
                  (double)xv.z * wa[2] + (double)xv.w * wa[3];
            lb += (double)xv.x * wb[0] + (double)xv.y * wb[1] +
                  (double)xv.z * wb[2] + (double)xv.w * wb[3];
        }
#pragma unroll
        for (int d = 1; d < 8; d <<= 1) {
            la += __shfl_xor_sync(mask8, la, d);
            lb += __shfl_xor_sync(mask8, lb, d);
        }
        la += (double)bg[ea];
        lb += (double)bg[eb];
        best = (lb > la) ? eb : ea;  // ea wins ties (first occurrence)
    }

    if (lane8 == 0) {
        int slot = atomicAdd(&g_count[best], 1);
        g_perm[best * N_MAX + slot] = tok;   // direct bucket write (order-free)
    }
}

// ---------------- stage 1: gate (2 tokens per 8-lane group) -----------------
#define GTOK 64   // tokens per block (32 groups x 2 tokens)
__global__ __launch_bounds__(256, 3) void gate_kernel(const float* __restrict__ x,
                                                      const float* __restrict__ Wg,
                                                      const float* __restrict__ bg,
                                                      const float* __restrict__ We,
                                                      int n_tokens) {
    __shared__ float Wgs[E * H];  // 32 KB
    int t = threadIdx.x;

    // fused We -> fp16 conversion (grid-stride over 4-elem chunks)
    for (int c = blockIdx.x * 256 + t; c < E * O * H / 4; c += gridDim.x * 256) {
        int i = c * 4;
        float4 v = *(const float4*)(We + i);
        *(uint2*)(g_whi + i) = make_uint2(cvt_h2(v.x, v.y), cvt_h2(v.z, v.w));
    }

    for (int i = t; i < E * H; i += 256) Wgs[i] = Wg[i];
    __syncthreads();

    int lane8 = t & 7;
    int grp = t >> 3;  // 0..31
    int tok0 = blockIdx.x * GTOK + grp;
    int tok1 = tok0 + 32;
    bool v0 = tok0 < n_tokens, v1 = tok1 < n_tokens;
    const float* xr0 = x + (size_t)tok0 * H;
    const float* xr1 = x + (size_t)tok1 * H;
    uint32_t mask8 = 0xFFu << ((t & 31) & 24);  // this group's 8 lanes

    float a0[E], a1[E];
#pragma unroll
    for (int e = 0; e < E; e++) { a0[e] = 0.f; a1[e] = 0.f; }

#pragma unroll 4
    for (int i = 0; i < H / 32; i++) {
        int k = i * 32 + lane8 * 4;
        float4 x0 = v0 ? *(const float4*)(xr0 + k) : make_float4(0.f, 0.f, 0.f, 0.f);
        float4 x1 = v1 ? *(const float4*)(xr1 + k) : make_float4(0.f, 0.f, 0.f, 0.f);
        if (v0)
            *(uint2*)(g_xhi + (size_t)tok0 * H + k) =
                make_uint2(cvt_h2(x0.x, x0.y), cvt_h2(x0.z, x0.w));
        if (v1)
            *(uint2*)(g_xhi + (size_t)tok1 * H + k) =
                make_uint2(cvt_h2(x1.x, x1.y), cvt_h2(x1.z, x1.w));
#pragma unroll
        for (int e = 0; e < E; e++) {
            float4 w = *(const float4*)(&Wgs[e * H + k]);  // one LDS, two tokens
            a0[e] += x0.x * w.x + x0.y * w.y + x0.z * w.z + x0.w * w.w;
            a1[e] += x1.x * w.x + x1.y * w.y + x1.z * w.z + x1.w * w.w;
        }
    }

    if (v0) finalize_token(xr0, Wgs, bg, a0, lane8, mask8, tok0);
    if (v1) finalize_token(xr1, Wgs, bg, a1, lane8, mask8, tok1);
}

// ---------------- stage 2: tile table; self-cleans g_count ----------------
__global__ void tile_kernel() {
    int lane = threadIdx.x;
    int c = (lane < E) ? g_count[lane] : 0;
    int nt = (c + BM - 1) / BM;
    int snt = nt;
#pragma unroll
    for (int d = 1; d < 32; d <<= 1) {
        int vn = __shfl_up_sync(0xFFFFFFFFu, snt, d);
        if (lane >= d) snt += vn;
    }
    int toff = snt - nt;
    if (lane < E) {
        g_ecnt[lane] = c;
        g_count[lane] = 0;  // restore invariant for next invocation
        for (int i = 0; i < nt; i++) {
            g_tile_e[toff + i] = lane;
            g_tile_m0[toff + i] = i * BM;
        }
    }
    if (lane == 31) g_ntiles = snt;
}

// ---------------- stage 3: fp16 HMMA gather-GEMM ----------------
__global__ __launch_bounds__(256, 2) void expert_gemm(const float* __restrict__ be,
                                                      float* __restrict__ out) {
    int tile = blockIdx.y;
    if (tile >= g_ntiles) return;
    int t = threadIdx.x;
    int e = g_tile_e[tile];
    int m0 = g_tile_m0[tile];
    int cnt = g_ecnt[e];
    int n0 = blockIdx.x * BN;

    extern __shared__ char smem[];
    int* rows = (int*)smem;
    float* bias_s = (float*)(smem + 512);
    float* stage = (float*)(smem + 1024);   // epilogue staging (aliases k-stages)
    uint32_t sb = smem_u32(smem);

    if (t < BM) {
        int m = m0 + t;
        rows[t] = (m < cnt) ? g_perm[e * N_MAX + m] : -1;
        bias_s[t] = be[e * O + n0 + t];
    }
    __syncthreads();

    uint32_t offA[4];
    uint32_t offB[4];
    int szA[4];
    uint32_t dsw[4];
#pragma unroll
    for (int g = 0; g < 4; g++) {
        int c = t + g * 256;
        int row = c >> 3, ch = c & 7;
        int r = rows[row];
        szA[g] = (r >= 0) ? 16 : 0;
        offA[g] = (uint32_t)(r < 0 ? 0 : r) * H + ch * 8;
        offB[g] = (uint32_t)(e * O + n0 + row) * H + ch * 8;
        dsw[g] = SWZ((uint32_t)(row * 128 + ch * 16));
    }

#define ISSUE_TILE(kt, bufbase)                                              \
    {                                                                        \
        int koff = (kt) * BKT;                                               \
        _Pragma("unroll") for (int g = 0; g < 4; g++) {                      \
            cp16((bufbase) + A_HI + dsw[g], g_xhi + offA[g] + koff, szA[g]); \
            cp16((bufbase) + B_HI + dsw[g], g_whi + offB[g] + koff, 16);     \
        }                                                                    \
        CP_COMMIT();                                                         \
    }

    int w = t >> 5, lane = t & 31;
    int warpM = w & 3, warpN = w >> 2;
    int grp = lane >> 3, lr = lane & 7;
    int arow = lr + (grp & 1) * 8;
    int akc = (grp >> 1) * 8;
    int brow = (grp >> 1) * 8 + lr;
    int bkc = (grp & 1) * 8;

    float acc[2][8][4];
#pragma unroll
    for (int i = 0; i < 2; i++)
#pragma unroll
        for (int j = 0; j < 8; j++)
#pragma unroll
            for (int c = 0; c < 4; c++) acc[i][j][c] = 0.f;

    uint32_t bufs[3] = {sb + 1024, sb + 1024 + STAGE_SZ, sb + 1024 + 2 * STAGE_SZ};

    ISSUE_TILE(0, bufs[0]);
    ISSUE_TILE(1, bufs[1]);

    for (int kt = 0; kt < KTILES; kt++) {
        if (kt < KTILES - 1) { CP_WAIT(1); } else { CP_WAIT(0); }
        __syncthreads();  // tile kt visible; reads of bufs[(kt+2)%3] (iter kt-1) done
        if (kt + 2 < KTILES) ISSUE_TILE(kt + 2, bufs[(kt + 2) % 3]);

        uint32_t bufb = bufs[kt % 3];
#pragma unroll
        for (int ks = 0; ks < 4; ks++) {
            uint32_t ah[2][4], bh[4][4];
#pragma unroll
            for (int mi = 0; mi < 2; mi++) {
                uint32_t off = SWZ((uint32_t)((warpM * 32 + mi * 16 + arow) * 128 +
                                              (ks * 16 + akc) * 2));
                ldsm4(ah[mi], bufb + A_HI + off);
            }
#pragma unroll
            for (int njp = 0; njp < 4; njp++) {
                uint32_t off = SWZ((uint32_t)((warpN * 64 + njp * 16 + brow) * 128 +
                                              (ks * 16 + bkc) * 2));
                ldsm4(bh[njp], bufb + B_HI + off);
            }
#pragma unroll
            for (int mi = 0; mi < 2; mi++)
#pragma unroll
                for (int njp = 0; njp < 4; njp++) {
                    mma_f16(acc[mi][njp * 2],     ah[mi], &bh[njp][0]);
                    mma_f16(acc[mi][njp * 2 + 1], ah[mi], &bh[njp][2]);
                }
        }
    }

    // ---- epilogue: fragments -> smem stage -> coalesced float4 stores ------
    __syncthreads();
    int qrow = lane >> 2, qcol = lane & 3;
#pragma unroll
    for (int mi = 0; mi < 2; mi++)
#pragma unroll
        for (int h = 0; h < 2; h++) {
            int m = warpM * 32 + mi * 16 + h * 8 + qrow;
            float* srow = stage + m * EPI_STRIDE + warpN * 64;
#pragma unroll
            for (int nj = 0; nj < 8; nj++) {
                int col = nj * 8 + qcol * 2;
                srow[col]     = acc[mi][nj][h * 2];
                srow[col + 1] = acc[mi][nj][h * 2 + 1];
            }
        }
    __syncthreads();

#pragma unroll
    for (int i = 0; i < 16; i++) {
        int idx = t + i * 256;
        int row = idx >> 5, c4 = idx & 31;
        int r = rows[row];
        if (r < 0) continue;
        const float* srow = stage + row * EPI_STRIDE + c4 * 4;
        float4 bv = *(const float4*)(bias_s + c4 * 4);
        float4 o;
        o.x = srow[0] + bv.x;
        o.y = srow[1] + bv.y;
        o.z = srow[2] + bv.z;
        o.w = srow[3] + bv.w;
        *(float4*)(out + (size_t)r * O + n0 + c4 * 4) = o;
    }
}

// ---------------- launch ----------------
extern "C" void kernel_launch(void* const* d_in, const int* in_sizes, int n_in,
                              void* d_out, int out_size) {
    const float* x  = (const float*)d_in[0];  // [N, H]
    const float* Wg = (const float*)d_in[1];  // [E, H]
    const float* bg = (const float*)d_in[2];  // [E]
    const float* We = (const float*)d_in[3];  // [E, O, H]
    const float* be = (const float*)d_in[4];  // [E, O]
    float* out = (float*)d_out;               // [N, O]

    int n_tokens = in_sizes[0] / H;

    cudaFuncSetAttribute(expert_gemm, cudaFuncAttributeMaxDynamicSharedMemorySize,
                         SMEM_TOTAL);

    gate_kernel<<<(n_tokens + GTOK - 1) / GTOK, 256>>>(x, Wg, bg, We, n_tokens);
    tile_kernel<<<1, 32>>>();

    dim3 grid(O / BN, MAX_TILES);
    expert_gemm<<<grid, 256, SMEM_TOTAL>>>(be, out);
}

// round 14
// speedup vs baseline: 1.1606x; 1.1606x over previous
#include <cuda_runtime.h>
#include <cuda_fp16.h>
#include <cstdint>

#define H 512
#define O 512
#define E 16
#define N_MAX 32768

#define BM 128          // tokens per CTA tile
#define BN 128          // outputs per CTA tile
#define BKT 64          // fp16 k-elements per smem tile (128B per row)
#define KTILES (H / BKT)
#define MAX_TILES 272

// ---------------- device scratch ----------------
__device__ int g_count[E];          // zeroed static; tile_kernel re-zeroes each run
__device__ int g_ecnt[E];
__device__ int g_perm[E * N_MAX];   // fixed-stride per-expert buckets (2 MB)
__device__ int g_tile_e[MAX_TILES];
__device__ int g_tile_m0[MAX_TILES];
__device__ int g_ntiles;

// pre-converted fp16 copies
__device__ uint16_t g_xhi[N_MAX * H];   // 32 MB
__device__ uint16_t g_whi[E * O * H];   // 8 MB

// ---------------- helpers ----------------
__device__ __forceinline__ uint32_t smem_u32(const void* p) {
    uint32_t a;
    asm("{ .reg .u64 t; cvta.to.shared.u64 t, %1; cvt.u32.u64 %0, t; }" : "=r"(a) : "l"(p));
    return a;
}
#define SWZ(o) ((o) ^ (((o) >> 3) & 0x70))

__device__ __forceinline__ uint32_t cvt_h2(float a, float b) {
    uint32_t hi;
    asm("cvt.rn.f16x2.f32 %0, %1, %2;" : "=r"(hi) : "f"(b), "f"(a));
    return hi;
}

__device__ __forceinline__ void ldsm4(uint32_t* r, uint32_t addr) {
    asm volatile("ldmatrix.sync.aligned.m8n8.x4.shared.b16 {%0,%1,%2,%3}, [%4];"
                 : "=r"(r[0]), "=r"(r[1]), "=r"(r[2]), "=r"(r[3]) : "r"(addr));
}

__device__ __forceinline__ void mma_f16(float* d, const uint32_t* a, const uint32_t* b) {
    asm volatile(
        "mma.sync.aligned.m16n8k16.row.col.f32.f16.f16.f32 "
        "{%0,%1,%2,%3}, {%4,%5,%6,%7}, {%8,%9}, {%0,%1,%2,%3};"
        : "+f"(d[0]), "+f"(d[1]), "+f"(d[2]), "+f"(d[3])
        : "r"(a[0]), "r"(a[1]), "r"(a[2]), "r"(a[3]), "r"(b[0]), "r"(b[1]));
}

__device__ __forceinline__ void cp16(uint32_t dst, const void* src, int srcsz) {
    asm volatile("cp.async.cg.shared.global [%0], [%1], 16, %2;"
                 :: "r"(dst), "l"(src), "r"(srcsz) : "memory");
}
#define CP_COMMIT() asm volatile("cp.async.commit_group;" ::: "memory")
#define CP_WAIT(n)  asm volatile("cp.async.wait_group %0;" :: "n"(n) : "memory")

// ---------------- smem layout (GEMM): 3 stages x 32KB -> 2 CTAs/SM ----------
#define STAGE_SZ 32768
#define A_HI 0
#define B_HI 16384
#define SMEM_TOTAL (1024 + 3 * STAGE_SZ)   // 99328 -> 2 CTAs/SM
#define EPI_STRIDE 132

// ---------------- gate: finalize one token (argmax + guard + bucket) --------
__device__ __forceinline__ void finalize_token(
    const float* __restrict__ xr, const float* __restrict__ Wgs,
    const float* __restrict__ bg, float* acc, int lane8, uint32_t mask8, int tok) {
    // butterfly reduce over the 8 lanes (all lanes identical after)
#pragma unroll
    for (int e = 0; e < E; e++) {
        acc[e] += __shfl_xor_sync(mask8, acc[e], 1);
        acc[e] += __shfl_xor_sync(mask8, acc[e], 2);
        acc[e] += __shfl_xor_sync(mask8, acc[e], 4);
        acc[e] += bg[e];
    }

    int best = 0;
    float bv = acc[0];
#pragma unroll
    for (int e = 1; e < E; e++)
        if (acc[e] > bv) { bv = acc[e]; best = e; }

    int sec = (best == 0) ? 1 : 0;
    float sv = acc[sec];
#pragma unroll
    for (int e = 0; e < E; e++)
        if (e != best && acc[e] > sv) { sv = acc[e]; sec = e; }

    if (bv - sv < 1e-3f) {
        // near-tie: 8-lane cooperative fp64 recompute of both candidates (cold)
        int ea = min(best, sec), eb = max(best, sec);
        double la = 0.0, lb = 0.0;
#pragma unroll 4
        for (int i = 0; i < H / 32; i++) {
            int k = i * 32 + lane8 * 4;
            float4 xv = *(const float4*)(xr + k);
            const float* wa = &Wgs[ea * H + k];
            const float* wb = &Wgs[eb * H + k];
            la += (double)xv.x * wa[0] + (double)xv.y * wa[1] +
                  (double)xv.z * wa[2] + (double)xv.w * wa[3];
            lb += (double)xv.x * wb[0] + (double)xv.y * wb[1] +
                  (double)xv.z * wb[2] + (double)xv.w * wb[3];
        }
#pragma unroll
        for (int d = 1; d < 8; d <<= 1) {
            la += __shfl_xor_sync(mask8, la, d);
            lb += __shfl_xor_sync(mask8, lb, d);
        }
        la += (double)bg[ea];
        lb += (double)bg[eb];
        best = (lb > la) ? eb : ea;  // ea wins ties (first occurrence)
    }

    if (lane8 == 0) {
        int slot = atomicAdd(&g_count[best], 1);
        g_perm[best * N_MAX + slot] = tok;   // direct bucket write (order-free)
    }
}

// ---------------- stage 1: gate (2 tokens per 8-lane group, 1 wave) ---------
#define GTOK 64   // tokens per block (32 groups x 2 tokens); 512 blocks = 1 wave @occ4
__global__ __launch_bounds__(256, 4) void gate_kernel(const float* __restrict__ x,
                                                      const float* __restrict__ Wg,
                                                      const float* __restrict__ bg,
                                                      const float* __restrict__ We,
                                                      int n_tokens) {
    __shared__ float Wgs[E * H];  // 32 KB
    int t = threadIdx.x;

    // fused We -> fp16 conversion (grid-stride over 4-elem chunks)
    for (int c = blockIdx.x * 256 + t; c < E * O * H / 4; c += gridDim.x * 256) {
        int i = c * 4;
        float4 v = *(const float4*)(We + i);
        *(uint2*)(g_whi + i) = make_uint2(cvt_h2(v.x, v.y), cvt_h2(v.z, v.w));
    }

    for (int i = t; i < E * H; i += 256) Wgs[i] = Wg[i];
    __syncthreads();

    int lane8 = t & 7;
    int grp = t >> 3;  // 0..31
    int tok0 = blockIdx.x * GTOK + grp;
    int tok1 = tok0 + 32;
    bool v0 = tok0 < n_tokens, v1 = tok1 < n_tokens;
    const float* xr0 = x + (size_t)tok0 * H;
    const float* xr1 = x + (size_t)tok1 * H;
    uint32_t mask8 = 0xFFu << ((t & 31) & 24);  // this group's 8 lanes

    float a0[E], a1[E];
#pragma unroll
    for (int e = 0; e < E; e++) { a0[e] = 0.f; a1[e] = 0.f; }

#pragma unroll
    for (int i = 0; i < H / 32; i++) {
        int k = i * 32 + lane8 * 4;
        float4 x0 = v0 ? *(const float4*)(xr0 + k) : make_float4(0.f, 0.f, 0.f, 0.f);
        float4 x1 = v1 ? *(const float4*)(xr1 + k) : make_float4(0.f, 0.f, 0.f, 0.f);
        if (v0)
            *(uint2*)(g_xhi + (size_t)tok0 * H + k) =
                make_uint2(cvt_h2(x0.x, x0.y), cvt_h2(x0.z, x0.w));
        if (v1)
            *(uint2*)(g_xhi + (size_t)tok1 * H + k) =
                make_uint2(cvt_h2(x1.x, x1.y), cvt_h2(x1.z, x1.w));
#pragma unroll
        for (int e = 0; e < E; e++) {
            float4 w = *(const float4*)(&Wgs[e * H + k]);  // one LDS, two tokens
            a0[e] += x0.x * w.x + x0.y * w.y + x0.z * w.z + x0.w * w.w;
            a1[e] += x1.x * w.x + x1.y * w.y + x1.z * w.z + x1.w * w.w;
        }
    }

    if (v0) finalize_token(xr0, Wgs, bg, a0, lane8, mask8, tok0);
    if (v1) finalize_token(xr1, Wgs, bg, a1, lane8, mask8, tok1);
}

// ---------------- stage 2: tile table; self-cleans g_count ----------------
__global__ void tile_kernel() {
    int lane = threadIdx.x;
    int c = (lane < E) ? g_count[lane] : 0;
    int nt = (c + BM - 1) / BM;
    int snt = nt;
#pragma unroll
    for (int d = 1; d < 32; d <<= 1) {
        int vn = __shfl_up_sync(0xFFFFFFFFu, snt, d);
        if (lane >= d) snt += vn;
    }
    int toff = snt - nt;
    if (lane < E) {
        g_ecnt[lane] = c;
        g_count[lane] = 0;  // restore invariant for next invocation
        for (int i = 0; i < nt; i++) {
            g_tile_e[toff + i] = lane;
            g_tile_m0[toff + i] = i * BM;
        }
    }
    if (lane == 31) g_ntiles = snt;
}

// ---------------- stage 3: fp16 HMMA gather-GEMM ----------------
__global__ __launch_bounds__(256, 2) void expert_gemm(const float* __restrict__ be,
                                                      float* __restrict__ out) {
    int tile = blockIdx.y;
    if (tile >= g_ntiles) return;
    int t = threadIdx.x;
    int e = g_tile_e[tile];
    int m0 = g_tile_m0[tile];
    int cnt = g_ecnt[e];
    int n0 = blockIdx.x * BN;

    extern __shared__ char smem[];
    int* rows = (int*)smem;
    float* bias_s = (float*)(smem + 512);
    float* stage = (float*)(smem + 1024);   // epilogue staging (aliases k-stages)
    uint32_t sb = smem_u32(smem);

    if (t < BM) {
        int m = m0 + t;
        rows[t] = (m < cnt) ? g_perm[e * N_MAX + m] : -1;
        bias_s[t] = be[e * O + n0 + t];
    }
    __syncthreads();

    uint32_t offA[4];
    uint32_t offB[4];
    int szA[4];
    uint32_t dsw[4];
#pragma unroll
    for (int g = 0; g < 4; g++) {
        int c = t + g * 256;
        int row = c >> 3, ch = c & 7;
        int r = rows[row];
        szA[g] = (r >= 0) ? 16 : 0;
        offA[g] = (uint32_t)(r < 0 ? 0 : r) * H + ch * 8;
        offB[g] = (uint32_t)(e * O + n0 + row) * H + ch * 8;
        dsw[g] = SWZ((uint32_t)(row * 128 + ch * 16));
    }

#define ISSUE_TILE(kt, bufbase)                                              \
    {                                                                        \
        int koff = (kt) * BKT;                                               \
        _Pragma("unroll") for (int g = 0; g < 4; g++) {                      \
            cp16((bufbase) + A_HI + dsw[g], g_xhi + offA[g] + koff, szA[g]); \
            cp16((bufbase) + B_HI + dsw[g], g_whi + offB[g] + koff, 16);     \
        }                                                                    \
        CP_COMMIT();                                                         \
    }

    int w = t >> 5, lane = t & 31;
    int warpM = w & 3, warpN = w >> 2;
    int grp = lane >> 3, lr = lane & 7;
    int arow = lr + (grp & 1) * 8;
    int akc = (grp >> 1) * 8;
    int brow = (grp >> 1) * 8 + lr;
    int bkc = (grp & 1) * 8;

    float acc[2][8][4];
#pragma unroll
    for (int i = 0; i < 2; i++)
#pragma unroll
        for (int j = 0; j < 8; j++)
#pragma unroll
            for (int c = 0; c < 4; c++) acc[i][j][c] = 0.f;

    uint32_t bufs[3] = {sb + 1024, sb + 1024 + STAGE_SZ, sb + 1024 + 2 * STAGE_SZ};

    ISSUE_TILE(0, bufs[0]);
    ISSUE_TILE(1, bufs[1]);

    for (int kt = 0; kt < KTILES; kt++) {
        if (kt < KTILES - 1) { CP_WAIT(1); } else { CP_WAIT(0); }
        __syncthreads();  // tile kt visible; reads of bufs[(kt+2)%3] (iter kt-1) done
        if (kt + 2 < KTILES) ISSUE_TILE(kt + 2, bufs[(kt + 2) % 3]);

        uint32_t bufb = bufs[kt % 3];
#pragma unroll
        for (int ks = 0; ks < 4; ks++) {
            uint32_t ah[2][4], bh[4][4];
#pragma unroll
            for (int mi = 0; mi < 2; mi++) {
                uint32_t off = SWZ((uint32_t)((warpM * 32 + mi * 16 + arow) * 128 +
                                              (ks * 16 + akc) * 2));
                ldsm4(ah[mi], bufb + A_HI + off);
            }
#pragma unroll
            for (int njp = 0; njp < 4; njp++) {
                uint32_t off = SWZ((uint32_t)((warpN * 64 + njp * 16 + brow) * 128 +
                                              (ks * 16 + bkc) * 2));
                ldsm4(bh[njp], bufb + B_HI + off);
            }
#pragma unroll
            for (int mi = 0; mi < 2; mi++)
#pragma unroll
                for (int njp = 0; njp < 4; njp++) {
                    mma_f16(acc[mi][njp * 2],     ah[mi], &bh[njp][0]);
                    mma_f16(acc[mi][njp * 2 + 1], ah[mi], &bh[njp][2]);
                }
        }
    }

    // ---- epilogue: fragments -> smem stage -> coalesced float4 stores ------
    __syncthreads();
    int qrow = lane >> 2, qcol = lane & 3;
#pragma unroll
    for (int mi = 0; mi < 2; mi++)
#pragma unroll
        for (int h = 0; h < 2; h++) {
            int m = warpM * 32 + mi * 16 + h * 8 + qrow;
            float* srow = stage + m * EPI_STRIDE + warpN * 64;
#pragma unroll
            for (int nj = 0; nj < 8; nj++) {
                int col = nj * 8 + qcol * 2;
                srow[col]     = acc[mi][nj][h * 2];
                srow[col + 1] = acc[mi][nj][h * 2 + 1];
            }
        }
    __syncthreads();

#pragma unroll
    for (int i = 0; i < 16; i++) {
        int idx = t + i * 256;
        int row = idx >> 5, c4 = idx & 31;
        int r = rows[row];
        if (r < 0) continue;
        const float* srow = stage + row * EPI_STRIDE + c4 * 4;
        float4 bv = *(const float4*)(bias_s + c4 * 4);
        float4 o;
        o.x = srow[0] + bv.x;
        o.y = srow[1] + bv.y;
        o.z = srow[2] + bv.z;
        o.w = srow[3] + bv.w;
        *(float4*)(out + (size_t)r * O + n0 + c4 * 4) = o;
    }
}

// ---------------- launch ----------------
extern "C" void kernel_launch(void* const* d_in, const int* in_sizes, int n_in,
                              void* d_out, int out_size) {
    const float* x  = (const float*)d_in[0];  // [N, H]
    const float* Wg = (const float*)d_in[1];  // [E, H]
    const float* bg = (const float*)d_in[2];  // [E]
    const float* We = (const float*)d_in[3];  // [E, O, H]
    const float* be = (const float*)d_in[4];  // [E, O]
    float* out = (float*)d_out;               // [N, O]

    int n_tokens = in_sizes[0] / H;

    cudaFuncSetAttribute(expert_gemm, cudaFuncAttributeMaxDynamicSharedMemorySize,
                         SMEM_TOTAL);

    gate_kernel<<<(n_tokens + GTOK - 1) / GTOK, 256>>>(x, Wg, bg, We, n_tokens);
    tile_kernel<<<1, 32>>>();

    dim3 grid(O / BN, MAX_TILES);
    expert_gemm<<<grid, 256, SMEM_TOTAL>>>(be, out);
}

// round 15
// speedup vs baseline: 1.2644x; 1.0894x over previous
#include <cuda_runtime.h>
#include <cuda_fp16.h>
#include <cstdint>

#define H 512
#define O 512
#define E 16
#define N_MAX 32768

#define BM 128          // tokens per CTA tile
#define BN 128          // outputs per CTA tile
#define BKT 64          // fp16 k-elements per smem tile (128B per row)
#define KTILES (H / BKT)
#define MAX_TILES 272

// ---------------- device scratch ----------------
__device__ int g_count[E];          // zeroed static; tile_kernel re-zeroes each run
__device__ int g_ecnt[E];
__device__ int g_perm[E * N_MAX];   // fixed-stride per-expert buckets (2 MB)
__device__ int g_tile_e[MAX_TILES];
__device__ int g_tile_m0[MAX_TILES];
__device__ int g_ntiles;

// pre-converted fp16 copies
__device__ uint16_t g_xhi[N_MAX * H];   // 32 MB
__device__ uint16_t g_whi[E * O * H];   // 8 MB

// ---------------- helpers ----------------
__device__ __forceinline__ uint32_t smem_u32(const void* p) {
    uint32_t a;
    asm("{ .reg .u64 t; cvta.to.shared.u64 t, %1; cvt.u32.u64 %0, t; }" : "=r"(a) : "l"(p));
    return a;
}
#define SWZ(o) ((o) ^ (((o) >> 3) & 0x70))

__device__ __forceinline__ uint32_t cvt_h2(float a, float b) {
    uint32_t hi;
    asm("cvt.rn.f16x2.f32 %0, %1, %2;" : "=r"(hi) : "f"(b), "f"(a));
    return hi;
}

__device__ __forceinline__ void ldsm4(uint32_t* r, uint32_t addr) {
    asm volatile("ldmatrix.sync.aligned.m8n8.x4.shared.b16 {%0,%1,%2,%3}, [%4];"
                 : "=r"(r[0]), "=r"(r[1]), "=r"(r[2]), "=r"(r[3]) : "r"(addr));
}

__device__ __forceinline__ void mma_f16(float* d, const uint32_t* a, const uint32_t* b) {
    asm volatile(
        "mma.sync.aligned.m16n8k16.row.col.f32.f16.f16.f32 "
        "{%0,%1,%2,%3}, {%4,%5,%6,%7}, {%8,%9}, {%0,%1,%2,%3};"
        : "+f"(d[0]), "+f"(d[1]), "+f"(d[2]), "+f"(d[3])
        : "r"(a[0]), "r"(a[1]), "r"(a[2]), "r"(a[3]), "r"(b[0]), "r"(b[1]));
}

__device__ __forceinline__ void cp16(uint32_t dst, const void* src, int srcsz) {
    asm volatile("cp.async.cg.shared.global [%0], [%1], 16, %2;"
                 :: "r"(dst), "l"(src), "r"(srcsz) : "memory");
}
#define CP_COMMIT() asm volatile("cp.async.commit_group;" ::: "memory")
#define CP_WAIT(n)  asm volatile("cp.async.wait_group %0;" :: "n"(n) : "memory")

// ---------------- smem layout (GEMM): 3 stages x 32KB -> 2 CTAs/SM ----------
#define STAGE_SZ 32768
#define A_HI 0
#define B_HI 16384
#define SMEM_TOTAL (1024 + 3 * STAGE_SZ)   // 99328 -> 2 CTAs/SM
#define EPI_STRIDE 132

// ---------------- gate: finalize one token (argmax + guard + bucket) --------
__device__ __forceinline__ void finalize_token(
    const float* __restrict__ xr, const float* __restrict__ Wgs,
    const float* __restrict__ bg, float* acc, int lane8, uint32_t mask8, int tok) {
    // butterfly reduce over the 8 lanes (all lanes identical after)
#pragma unroll
    for (int e = 0; e < E; e++) {
        acc[e] += __shfl_xor_sync(mask8, acc[e], 1);
        acc[e] += __shfl_xor_sync(mask8, acc[e], 2);
        acc[e] += __shfl_xor_sync(mask8, acc[e], 4);
        acc[e] += bg[e];
    }

    int best = 0;
    float bv = acc[0];
#pragma unroll
    for (int e = 1; e < E; e++)
        if (acc[e] > bv) { bv = acc[e]; best = e; }

    int sec = (best == 0) ? 1 : 0;
    float sv = acc[sec];
#pragma unroll
    for (int e = 0; e < E; e++)
        if (e != best && acc[e] > sv) { sv = acc[e]; sec = e; }

    if (bv - sv < 1e-3f) {
        // near-tie: 8-lane cooperative fp64 recompute of both candidates (cold)
        int ea = min(best, sec), eb = max(best, sec);
        double la = 0.0, lb = 0.0;
#pragma unroll 4
        for (int i = 0; i < H / 32; i++) {
            int k = i * 32 + lane8 * 4;
            float4 xv = *(const float4*)(xr + k);
            const float* wa = &Wgs[ea * H + k];
            const float* wb = &Wgs[eb * H + k];
            la += (double)xv.x * wa[0] + (double)xv.y * wa[1] +
                  (double)xv.z * wa[2] + (double)xv.w * wa[3];
            lb += (double)xv.x * wb[0] + (double)xv.y * wb[1] +
                  (double)xv.z * wb[2] + (double)xv.w * wb[3];
        }
#pragma unroll
        for (int d = 1; d < 8; d <<= 1) {
            la += __shfl_xor_sync(mask8, la, d);
            lb += __shfl_xor_sync(mask8, lb, d);
        }
        la += (double)bg[ea];
        lb += (double)bg[eb];
        best = (lb > la) ? eb : ea;  // ea wins ties (first occurrence)
    }

    if (lane8 == 0) {
        int slot = atomicAdd(&g_count[best], 1);
        g_perm[best * N_MAX + slot] = tok;   // direct bucket write (order-free)
    }
}

// ---------------- stage 1: gate (2 tokens/group, 2 expert passes, 1 wave) ---
#define GTOK 64   // tokens per block (32 groups x 2 tokens); 512 blocks = 1 wave @occ4
__global__ __launch_bounds__(256, 4) void gate_kernel(const float* __restrict__ x,
                                                      const float* __restrict__ Wg,
                                                      const float* __restrict__ bg,
                                                      const float* __restrict__ We,
                                                      int n_tokens) {
    __shared__ float Wgs[E * H];  // 32 KB
    int t = threadIdx.x;

    // fused We -> fp16 conversion (grid-stride over 4-elem chunks)
    for (int c = blockIdx.x * 256 + t; c < E * O * H / 4; c += gridDim.x * 256) {
        int i = c * 4;
        float4 v = *(const float4*)(We + i);
        *(uint2*)(g_whi + i) = make_uint2(cvt_h2(v.x, v.y), cvt_h2(v.z, v.w));
    }

    for (int i = t; i < E * H; i += 256) Wgs[i] = Wg[i];
    __syncthreads();

    int lane8 = t & 7;
    int grp = t >> 3;  // 0..31
    int tok0 = blockIdx.x * GTOK + grp;
    int tok1 = tok0 + 32;
    bool v0 = tok0 < n_tokens, v1 = tok1 < n_tokens;
    const float* xr0 = x + (size_t)tok0 * H;
    const float* xr1 = x + (size_t)tok1 * H;
    uint32_t mask8 = 0xFFu << ((t & 31) & 24);  // this group's 8 lanes

    float acc0[E], acc1[E];

    // ---- pass 1: experts 0..7, plus x -> fp16 convert+store ----
    {
        float a0[8], a1[8];
#pragma unroll
        for (int e = 0; e < 8; e++) { a0[e] = 0.f; a1[e] = 0.f; }
#pragma unroll
        for (int i = 0; i < H / 32; i++) {
            int k = i * 32 + lane8 * 4;
            float4 x0 = v0 ? *(const float4*)(xr0 + k) : make_float4(0.f, 0.f, 0.f, 0.f);
            float4 x1 = v1 ? *(const float4*)(xr1 + k) : make_float4(0.f, 0.f, 0.f, 0.f);
            if (v0)
                *(uint2*)(g_xhi + (size_t)tok0 * H + k) =
                    make_uint2(cvt_h2(x0.x, x0.y), cvt_h2(x0.z, x0.w));
            if (v1)
                *(uint2*)(g_xhi + (size_t)tok1 * H + k) =
                    make_uint2(cvt_h2(x1.x, x1.y), cvt_h2(x1.z, x1.w));
#pragma unroll
            for (int e = 0; e < 8; e++) {
                float4 w = *(const float4*)(&Wgs[e * H + k]);  // one LDS, two tokens
                a0[e] += x0.x * w.x + x0.y * w.y + x0.z * w.z + x0.w * w.w;
                a1[e] += x1.x * w.x + x1.y * w.y + x1.z * w.z + x1.w * w.w;
            }
        }
#pragma unroll
        for (int e = 0; e < 8; e++) { acc0[e] = a0[e]; acc1[e] = a1[e]; }
    }

    // ---- pass 2: experts 8..15 (x re-streamed; L1/L2 resident) ----
    {
        float a0[8], a1[8];
#pragma unroll
        for (int e = 0; e < 8; e++) { a0[e] = 0.f; a1[e] = 0.f; }
#pragma unroll
        for (int i = 0; i < H / 32; i++) {
            int k = i * 32 + lane8 * 4;
            float4 x0 = v0 ? *(const float4*)(xr0 + k) : make_float4(0.f, 0.f, 0.f, 0.f);
            float4 x1 = v1 ? *(const float4*)(xr1 + k) : make_float4(0.f, 0.f, 0.f, 0.f);
#pragma unroll
            for (int e = 0; e < 8; e++) {
                float4 w = *(const float4*)(&Wgs[(e + 8) * H + k]);
                a0[e] += x0.x * w.x + x0.y * w.y + x0.z * w.z + x0.w * w.w;
                a1[e] += x1.x * w.x + x1.y * w.y + x1.z * w.z + x1.w * w.w;
            }
        }
#pragma unroll
        for (int e = 0; e < 8; e++) { acc0[e + 8] = a0[e]; acc1[e + 8] = a1[e]; }
    }

    if (v0) finalize_token(xr0, Wgs, bg, acc0, lane8, mask8, tok0);
    if (v1) finalize_token(xr1, Wgs, bg, acc1, lane8, mask8, tok1);
}

// ---------------- stage 2: tile table; self-cleans g_count ----------------
__global__ void tile_kernel() {
    int lane = threadIdx.x;
    int c = (lane < E) ? g_count[lane] : 0;
    int nt = (c + BM - 1) / BM;
    int snt = nt;
#pragma unroll
    for (int d = 1; d < 32; d <<= 1) {
        int vn = __shfl_up_sync(0xFFFFFFFFu, snt, d);
        if (lane >= d) snt += vn;
    }
    int toff = snt - nt;
    if (lane < E) {
        g_ecnt[lane] = c;
        g_count[lane] = 0;  // restore invariant for next invocation
        for (int i = 0; i < nt; i++) {
            g_tile_e[toff + i] = lane;
            g_tile_m0[toff + i] = i * BM;
        }
    }
    if (lane == 31) g_ntiles = snt;
}

// ---------------- stage 3: fp16 HMMA gather-GEMM ----------------
__global__ __launch_bounds__(256, 2) void expert_gemm(const float* __restrict__ be,
                                                      float* __restrict__ out) {
    int tile = blockIdx.y;
    if (tile >= g_ntiles) return;
    int t = threadIdx.x;
    int e = g_tile_e[tile];
    int m0 = g_tile_m0[tile];
    int cnt = g_ecnt[e];
    int n0 = blockIdx.x * BN;

    extern __shared__ char smem[];
    int* rows = (int*)smem;
    float* bias_s = (float*)(smem + 512);
    float* stage = (float*)(smem + 1024);   // epilogue staging (aliases k-stages)
    uint32_t sb = smem_u32(smem);

    if (t < BM) {
        int m = m0 + t;
        rows[t] = (m < cnt) ? g_perm[e * N_MAX + m] : -1;
        bias_s[t] = be[e * O + n0 + t];
    }
    __syncthreads();

    uint32_t offA[4];
    uint32_t offB[4];
    int szA[4];
    uint32_t dsw[4];
#pragma unroll
    for (int g = 0; g < 4; g++) {
        int c = t + g * 256;
        int row = c >> 3, ch = c & 7;
        int r = rows[row];
        szA[g] = (r >= 0) ? 16 : 0;
        offA[g] = (uint32_t)(r < 0 ? 0 : r) * H + ch * 8;
        offB[g] = (uint32_t)(e * O + n0 + row) * H + ch * 8;
        dsw[g] = SWZ((uint32_t)(row * 128 + ch * 16));
    }

#define ISSUE_TILE(kt, bufbase)                                              \
    {                                                                        \
        int koff = (kt) * BKT;                                               \
        _Pragma("unroll") for (int g = 0; g < 4; g++) {                      \
            cp16((bufbase) + A_HI + dsw[g], g_xhi + offA[g] + koff, szA[g]); \
            cp16((bufbase) + B_HI + dsw[g], g_whi + offB[g] + koff, 16);     \
        }                                                                    \
        CP_COMMIT();                                                         \
    }

    int w = t >> 5, lane = t & 31;
    int warpM = w & 3, warpN = w >> 2;
    int grp = lane >> 3, lr = lane & 7;
    int arow = lr + (grp & 1) * 8;
    int akc = (grp >> 1) * 8;
    int brow = (grp >> 1) * 8 + lr;
    int bkc = (grp & 1) * 8;

    float acc[2][8][4];
#pragma unroll
    for (int i = 0; i < 2; i++)
#pragma unroll
        for (int j = 0; j < 8; j++)
#pragma unroll
            for (int c = 0; c < 4; c++) acc[i][j][c] = 0.f;

    uint32_t bufs[3] = {sb + 1024, sb + 1024 + STAGE_SZ, sb + 1024 + 2 * STAGE_SZ};

    ISSUE_TILE(0, bufs[0]);
    ISSUE_TILE(1, bufs[1]);

    for (int kt = 0; kt < KTILES; kt++) {
        if (kt < KTILES - 1) { CP_WAIT(1); } else { CP_WAIT(0); }
        __syncthreads();  // tile kt visible; reads of bufs[(kt+2)%3] (iter kt-1) done
        if (kt + 2 < KTILES) ISSUE_TILE(kt + 2, bufs[(kt + 2) % 3]);

        uint32_t bufb = bufs[kt % 3];
#pragma unroll
        for (int ks = 0; ks < 4; ks++) {
            uint32_t ah[2][4], bh[4][4];
#pragma unroll
            for (int mi = 0; mi < 2; mi++) {
                uint32_t off = SWZ((uint32_t)((warpM * 32 + mi * 16 + arow) * 128 +
                                              (ks * 16 + akc) * 2));
                ldsm4(ah[mi], bufb + A_HI + off);
            }
#pragma unroll
            for (int njp = 0; njp < 4; njp++) {
                uint32_t off = SWZ((uint32_t)((warpN * 64 + njp * 16 + brow) * 128 +
                                              (ks * 16 + bkc) * 2));
                ldsm4(bh[njp], bufb + B_HI + off);
            }
#pragma unroll
            for (int mi = 0; mi < 2; mi++)
#pragma unroll
                for (int njp = 0; njp < 4; njp++) {
                    mma_f16(acc[mi][njp * 2],     ah[mi], &bh[njp][0]);
                    mma_f16(acc[mi][njp * 2 + 1], ah[mi], &bh[njp][2]);
                }
        }
    }

    // ---- epilogue: fragments -> smem stage -> coalesced float4 stores ------
    __syncthreads();
    int qrow = lane >> 2, qcol = lane & 3;
#pragma unroll
    for (int mi = 0; mi < 2; mi++)
#pragma unroll
        for (int h = 0; h < 2; h++) {
            int m = warpM * 32 + mi * 16 + h * 8 + qrow;
            float* srow = stage + m * EPI_STRIDE + warpN * 64;
#pragma unroll
            for (int nj = 0; nj < 8; nj++) {
                int col = nj * 8 + qcol * 2;
                srow[col]     = acc[mi][nj][h * 2];
                srow[col + 1] = acc[mi][nj][h * 2 + 1];
            }
        }
    __syncthreads();

#pragma unroll
    for (int i = 0; i < 16; i++) {
        int idx = t + i * 256;
        int row = idx >> 5, c4 = idx & 31;
        int r = rows[row];
        if (r < 0) continue;
        const float* srow = stage + row * EPI_STRIDE + c4 * 4;
        float4 bv = *(const float4*)(bias_s + c4 * 4);
        float4 o;
        o.x = srow[0] + bv.x;
        o.y = srow[1] + bv.y;
        o.z = srow[2] + bv.z;
        o.w = srow[3] + bv.w;
        *(float4*)(out + (size_t)r * O + n0 + c4 * 4) = o;
    }
}

// ---------------- launch ----------------
extern "C" void kernel_launch(void* const* d_in, const int* in_sizes, int n_in,
                              void* d_out, int out_size) {
    const float* x  = (const float*)d_in[0];  // [N, H]
    const float* Wg = (const float*)d_in[1];  // [E, H]
    const float* bg = (const float*)d_in[2];  // [E]
    const float* We = (const float*)d_in[3];  // [E, O, H]
    const float* be = (const float*)d_in[4];  // [E, O]
    float* out = (float*)d_out;               // [N, O]

    int n_tokens = in_sizes[0] / H;

    cudaFuncSetAttribute(expert_gemm, cudaFuncAttributeMaxDynamicSharedMemorySize,
                         SMEM_TOTAL);

    gate_kernel<<<(n_tokens + GTOK - 1) / GTOK, 256>>>(x, Wg, bg, We, n_tokens);
    tile_kernel<<<1, 32>>>();

    dim3 grid(O / BN, MAX_TILES);
    expert_gemm<<<grid, 256, SMEM_TOTAL>>>(be, out);
}